// round 1
// baseline (speedup 1.0000x reference)
#include <cuda_runtime.h>

#define NEMB 1024
#define HS 64
#define BB 8
#define TT 2048
#define BT (BB * TT)

#define PAD 68  // smem row stride (floats) for 64-wide padded tiles; %4==0 for float4

// Scratch for projected Q, K, V (allocation-free: __device__ globals)
__device__ float g_Q[BT * HS];
__device__ float g_K[BT * HS];
__device__ float g_V[BT * HS];

// ---------------------------------------------------------------------------
// Projection GEMM: C = X @ W   (X: BT x NEMB, W: NEMB x HS)
// BM=64, BN=64(=HS), KT=16. 256 threads as 16x16, each owns 4x4 microtile.
// blockIdx.y selects which of Wq/Wk/Wv (and target buffer).
// ---------------------------------------------------------------------------
__global__ __launch_bounds__(256) void proj_kernel(
    const float* __restrict__ x,
    const float* __restrict__ Wq,
    const float* __restrict__ Wk,
    const float* __restrict__ Wv)
{
    __shared__ float Xs[64][20];   // 64 rows x 16 k (pad 20 for alignment)
    __shared__ float Ws[16][64];   // 16 k x 64 n

    const float* W = (blockIdx.y == 0) ? Wq : (blockIdx.y == 1) ? Wk : Wv;
    float* C = (blockIdx.y == 0) ? g_Q : (blockIdx.y == 1) ? g_K : g_V;

    const int bt0 = blockIdx.x * 64;
    const int tid = threadIdx.x;
    const int tx = tid & 15;
    const int ty = tid >> 4;

    // loader indices
    const int xr = tid >> 2;            // 0..63
    const int xc = (tid & 3) * 4;       // 0,4,8,12
    const int wk = tid >> 4;            // 0..15
    const int wn = (tid & 15) * 4;      // 0..60

    float acc[4][4] = {};

    for (int kt = 0; kt < NEMB / 16; ++kt) {
        // load X tile 64x16 (float4, coalesced)
        float4 xv = *(const float4*)&x[(size_t)(bt0 + xr) * NEMB + kt * 16 + xc];
        *(float4*)&Xs[xr][xc] = xv;
        // load W tile 16x64 (float4, coalesced)
        float4 wv = *(const float4*)&W[(size_t)(kt * 16 + wk) * HS + wn];
        *(float4*)&Ws[wk][wn] = wv;
        __syncthreads();

        #pragma unroll
        for (int k4 = 0; k4 < 4; ++k4) {
            float a[4][4];   // [i][kk]
            float b[4][4];   // [kk][j]
            #pragma unroll
            for (int i = 0; i < 4; ++i) {
                float4 t = *(const float4*)&Xs[ty + 16 * i][k4 * 4];
                a[i][0] = t.x; a[i][1] = t.y; a[i][2] = t.z; a[i][3] = t.w;
            }
            #pragma unroll
            for (int kk = 0; kk < 4; ++kk) {
                float4 t = *(const float4*)&Ws[k4 * 4 + kk][tx * 4];
                b[kk][0] = t.x; b[kk][1] = t.y; b[kk][2] = t.z; b[kk][3] = t.w;
            }
            #pragma unroll
            for (int i = 0; i < 4; ++i)
                #pragma unroll
                for (int j = 0; j < 4; ++j)
                    #pragma unroll
                    for (int kk = 0; kk < 4; ++kk)
                        acc[i][j] += a[i][kk] * b[kk][j];
        }
        __syncthreads();
    }

    #pragma unroll
    for (int i = 0; i < 4; ++i) {
        float4 o;
        o.x = acc[i][0]; o.y = acc[i][1]; o.z = acc[i][2]; o.w = acc[i][3];
        *(float4*)&C[(size_t)(bt0 + ty + 16 * i) * HS + tx * 4] = o;
    }
}

// ---------------------------------------------------------------------------
// Fused causal attention with online softmax (flash-style), fp32.
// One CTA per (batch, 64-query tile). 256 threads as 16x16.
//   S GEMM mapping:  row = ty+16i (query), col = tx+16j (key)
//   PV/out mapping:  row = ty+16i (query), dim = tx*4+j  (head dim)
// Row-group softmax reductions happen across the 16 tx-lanes (shfl_xor 8/4/2/1).
// ---------------------------------------------------------------------------
__global__ __launch_bounds__(256) void attn_kernel(float* __restrict__ out)
{
    extern __shared__ float sm[];
    float* Qs = sm;                    // 64 x PAD
    float* Ks = sm + 64 * PAD;         // 64 x PAD
    float* Ps = sm + 2 * 64 * PAD;     // 64 x PAD
    float* Vs = sm + 3 * 64 * PAD;     // 64 x 64 (unpadded)

    const int b  = blockIdx.y;
    const int qt = gridDim.x - 1 - blockIdx.x;   // heavy tiles first
    const int t0 = qt * 64;
    const int tid = threadIdx.x;
    const int tx = tid & 15;
    const int ty = tid >> 4;

    const float NEG_INF = -1e30f;

    // Load Q tile (contiguous 4096 floats)
    {
        const float4* Qg = (const float4*)(g_Q + (size_t)(b * TT + t0) * HS);
        #pragma unroll
        for (int r = 0; r < 4; ++r) {
            int idx = tid + 256 * r;
            int row = idx >> 4;
            int c   = (idx & 15) * 4;
            *(float4*)&Qs[row * PAD + c] = Qg[idx];
        }
    }

    float acc[4][4] = {};
    float m[4], l[4];
    #pragma unroll
    for (int i = 0; i < 4; ++i) { m[i] = NEG_INF; l[i] = 0.0f; }

    for (int kt = 0; kt <= qt; ++kt) {
        __syncthreads();  // protect K/V/P from readers of the previous iteration

        // Load K and V tiles (each contiguous 4096 floats)
        {
            const float4* Kg = (const float4*)(g_K + (size_t)(b * TT + kt * 64) * HS);
            const float4* Vg = (const float4*)(g_V + (size_t)(b * TT + kt * 64) * HS);
            #pragma unroll
            for (int r = 0; r < 4; ++r) {
                int idx = tid + 256 * r;
                int row = idx >> 4;
                int c   = (idx & 15) * 4;
                *(float4*)&Ks[row * PAD + c] = Kg[idx];
                *(float4*)&Vs[row * 64 + c]  = Vg[idx];
            }
        }
        __syncthreads();

        // S = Q K^T (64x64x64), per-thread 4x4 at (ty+16i, tx+16j)
        float s[4][4] = {};
        #pragma unroll
        for (int h4 = 0; h4 < 16; ++h4) {
            float a[4][4];   // [i][hh]
            float kx[4][4];  // [j][hh]
            #pragma unroll
            for (int i = 0; i < 4; ++i) {
                float4 t = *(const float4*)&Qs[(ty + 16 * i) * PAD + h4 * 4];
                a[i][0] = t.x; a[i][1] = t.y; a[i][2] = t.z; a[i][3] = t.w;
            }
            #pragma unroll
            for (int j = 0; j < 4; ++j) {
                float4 t = *(const float4*)&Ks[(tx + 16 * j) * PAD + h4 * 4];
                kx[j][0] = t.x; kx[j][1] = t.y; kx[j][2] = t.z; kx[j][3] = t.w;
            }
            #pragma unroll
            for (int i = 0; i < 4; ++i)
                #pragma unroll
                for (int j = 0; j < 4; ++j)
                    #pragma unroll
                    for (int hh = 0; hh < 4; ++hh)
                        s[i][j] += a[i][hh] * kx[j][hh];
        }

        // Causal mask (only diagonal tile needs it)
        if (kt == qt) {
            #pragma unroll
            for (int i = 0; i < 4; ++i)
                #pragma unroll
                for (int j = 0; j < 4; ++j)
                    if ((tx + 16 * j) > (ty + 16 * i)) s[i][j] = NEG_INF;
        }

        // Online softmax update + write P
        #pragma unroll
        for (int i = 0; i < 4; ++i) {
            float mx = fmaxf(fmaxf(s[i][0], s[i][1]), fmaxf(s[i][2], s[i][3]));
            #pragma unroll
            for (int off = 8; off >= 1; off >>= 1)
                mx = fmaxf(mx, __shfl_xor_sync(0xffffffffu, mx, off));
            float mnew  = fmaxf(m[i], mx);
            float alpha = __expf(m[i] - mnew);
            float sum = 0.0f;
            #pragma unroll
            for (int j = 0; j < 4; ++j) {
                float p = __expf(s[i][j] - mnew);
                Ps[(ty + 16 * i) * PAD + tx + 16 * j] = p;
                sum += p;
            }
            #pragma unroll
            for (int off = 8; off >= 1; off >>= 1)
                sum += __shfl_xor_sync(0xffffffffu, sum, off);
            l[i] = l[i] * alpha + sum;
            m[i] = mnew;
            #pragma unroll
            for (int j = 0; j < 4; ++j) acc[i][j] *= alpha;
        }
        __syncthreads();

        // acc += P @ V  (64x64x64), per-thread 4x4 at (ty+16i, tx*4+j)
        #pragma unroll
        for (int s4 = 0; s4 < 16; ++s4) {
            float p[4][4];   // [i][ss]
            float v[4][4];   // [ss][j]
            #pragma unroll
            for (int i = 0; i < 4; ++i) {
                float4 t = *(const float4*)&Ps[(ty + 16 * i) * PAD + s4 * 4];
                p[i][0] = t.x; p[i][1] = t.y; p[i][2] = t.z; p[i][3] = t.w;
            }
            #pragma unroll
            for (int ss = 0; ss < 4; ++ss) {
                float4 t = *(const float4*)&Vs[(s4 * 4 + ss) * 64 + tx * 4];
                v[ss][0] = t.x; v[ss][1] = t.y; v[ss][2] = t.z; v[ss][3] = t.w;
            }
            #pragma unroll
            for (int i = 0; i < 4; ++i)
                #pragma unroll
                for (int j = 0; j < 4; ++j)
                    #pragma unroll
                    for (int ss = 0; ss < 4; ++ss)
                        acc[i][j] += p[i][ss] * v[ss][j];
        }
    }

    // Epilogue: out = acc / l
    #pragma unroll
    for (int i = 0; i < 4; ++i) {
        float inv = 1.0f / l[i];
        float4 o;
        o.x = acc[i][0] * inv; o.y = acc[i][1] * inv;
        o.z = acc[i][2] * inv; o.w = acc[i][3] * inv;
        *(float4*)&out[(size_t)(b * TT + t0 + ty + 16 * i) * HS + tx * 4] = o;
    }
}

// ---------------------------------------------------------------------------

static const int ATTN_SMEM = (3 * 64 * PAD + 64 * 64) * (int)sizeof(float);  // 68608 B

extern "C" void kernel_launch(void* const* d_in, const int* in_sizes, int n_in,
                              void* d_out, int out_size)
{
    const float* x  = (const float*)d_in[0];
    const float* Wq = (const float*)d_in[1];
    const float* Wk = (const float*)d_in[2];
    const float* Wv = (const float*)d_in[3];
    float* out = (float*)d_out;

    (void)in_sizes; (void)n_in; (void)out_size;

    cudaFuncSetAttribute(attn_kernel, cudaFuncAttributeMaxDynamicSharedMemorySize,
                         ATTN_SMEM);

    proj_kernel<<<dim3(BT / 64, 3), 256>>>(x, Wq, Wk, Wv);
    attn_kernel<<<dim3(TT / 64, BB), 256, ATTN_SMEM>>>(out);
}